// round 3
// baseline (speedup 1.0000x reference)
#include <cuda_runtime.h>
#include <cstdint>

// ---------------------------------------------------------------------------
// QLSTM: the reference collapses algebraically:
//   * each gate uses only W[0,:] -> theta is a scalar per batch element
//   * _expval(theta,U) = alpha + R*cos(theta - phi)   (3 consts per gate)
//   * f,i,g,o are scalars per batch row -> c[b,:], h[b,:] are uniform over H
// Pipeline: (A) circuit consts, (B) x-projection, (C) scalar scan, (D) broadcast.
// ---------------------------------------------------------------------------

#define T_STEPS 256
#define BATCH   128
#define D_INPUT 512
#define HID     512
#define ROWS    (T_STEPS * BATCH)   // 32768
#define DIMQ    256                 // 2^8

// scratch (static device globals; no allocation)
__device__ float4 g_z[ROWS];        // per (t,b): theta contribution from x, per gate (bias-phi folded)
__device__ float  g_h[ROWS];        // h scalar per (t,b)
__device__ float  g_cfin[BATCH];    // final c scalar per b
__device__ float  g_gate[4][8];     // per gate: alpha, R, phi, sW(hidden half), b0

struct GatePtrs {
    const float* W[4];
    const float* b[4];
    const float* P[4];
};

__device__ __forceinline__ float2 cmul(float2 a, float2 b) {
    return make_float2(a.x * b.x - a.y * b.y, a.x * b.y + a.y * b.x);
}

// prefix-XOR from MSB = CNOT-chain permutation on 8-bit basis index
__device__ __forceinline__ int chain_perm(int k) {
    k ^= k >> 1; k ^= k >> 2; k ^= k >> 4;
    return k & 0xFF;
}

// ======================= Kernel A: circuit constants =======================
__global__ void gate_const_kernel(GatePtrs gp) {
    const int g = blockIdx.x;      // gate 0..3 (f,i,g,o)
    const int k = threadIdx.x;     // basis index 0..255

    __shared__ float2 rot[2][8][2][2];
    __shared__ float2 u0[DIMQ];
    __shared__ float2 u1[DIMQ];
    __shared__ float  rbuf[4][8];

    const float* P = gp.P[g];
    if (k < 16) {
        int l = k >> 3, w = k & 7;
        float phi = P[(l * 8 + w) * 3 + 0];
        float th  = P[(l * 8 + w) * 3 + 1];
        float om  = P[(l * 8 + w) * 3 + 2];
        float s, c;
        sincosf(0.5f * th, &s, &c);
        float hp = 0.5f * (phi + om);
        float hm = 0.5f * (phi - om);
        float2 ep = make_float2(cosf(hp), -sinf(hp)); // exp(-i(phi+om)/2)
        float2 em = make_float2(cosf(hm),  sinf(hm)); // exp(+i(phi-om)/2)
        rot[l][w][0][0] = make_float2( ep.x * c,  ep.y * c);
        rot[l][w][0][1] = make_float2(-em.x * s, -em.y * s);
        rot[l][w][1][0] = make_float2( em.x * s, -em.y * s);  // conj(em)*s
        rot[l][w][1][1] = make_float2( ep.x * c, -ep.y * c);  // conj(ep)*c
    }
    __syncthreads();

    // layer-1 columns (kron product -> per-element product of scalars)
    // wire w <-> bit position (7-w); column index bits: e0 -> all 0; e128 -> wire0=1
    float2 a0 = make_float2(1.f, 0.f);
    float2 a1 = make_float2(1.f, 0.f);
    #pragma unroll
    for (int w = 0; w < 8; ++w) {
        int kb = (k >> (7 - w)) & 1;
        a0 = cmul(a0, rot[0][w][kb][0]);
        a1 = cmul(a1, rot[0][w][kb][(w == 0) ? 1 : 0]);
    }

    const int pk = chain_perm(k);
    u0[pk] = a0;
    u1[pk] = a1;
    __syncthreads();

    // apply layer 2, one wire at a time
    #pragma unroll
    for (int w = 0; w < 8; ++w) {
        int p = 7 - w, m = 1 << p, kb = (k >> p) & 1;
        float2 x0 = u0[k & ~m], x1 = u0[k | m];
        float2 y0 = u1[k & ~m], y1 = u1[k | m];
        __syncthreads();
        float2 r0 = rot[1][w][kb][0];
        float2 r1 = rot[1][w][kb][1];
        u0[k] = make_float2(r0.x * x0.x - r0.y * x0.y + r1.x * x1.x - r1.y * x1.y,
                            r0.x * x0.y + r0.y * x0.x + r1.x * x1.y + r1.y * x1.x);
        u1[k] = make_float2(r0.x * y0.x - r0.y * y0.y + r1.x * y1.x - r1.y * y1.y,
                            r0.x * y0.y + r0.y * y0.x + r1.x * y1.y + r1.y * y1.x);
        __syncthreads();
    }

    // final CNOT-chain permutation
    float2 c0 = u0[k], c1 = u1[k];
    __syncthreads();
    u0[pk] = c0; u1[pk] = c1;
    __syncthreads();
    c0 = u0[k]; c1 = u1[k];

    // <Z0> pieces
    float z0 = (k < 128) ? 1.f : -1.f;
    float A  = z0 * (c0.x * c0.x + c0.y * c0.y);
    float B  = z0 * (c1.x * c1.x + c1.y * c1.y);
    float C  = -2.f * z0 * (c0.y * c1.x - c0.x * c1.y);   // -2 Z0 Im(c0 * conj(c1))

    // sW = sum of W[0][512..1023]
    const float* W = gp.W[g];
    float sw = W[512 + k] + W[768 + k];

    float vals[4] = {A, B, C, sw};
    int lane = k & 31, warp = k >> 5;
    #pragma unroll
    for (int i = 0; i < 4; ++i) {
        float x = vals[i];
        #pragma unroll
        for (int off = 16; off; off >>= 1)
            x += __shfl_xor_sync(0xffffffffu, x, off);
        if (lane == 0) rbuf[i][warp] = x;
    }
    __syncthreads();
    if (k == 0) {
        float t[4];
        #pragma unroll
        for (int i = 0; i < 4; ++i) {
            float s = 0.f;
            #pragma unroll
            for (int wv = 0; wv < 8; ++wv) s += rbuf[i][wv];
            t[i] = s;
        }
        float alpha = 0.5f * (t[0] + t[1]);
        float beta  = 0.5f * (t[0] - t[1]);
        float gamma = 0.5f * t[2];
        float R     = sqrtf(beta * beta + gamma * gamma);
        float phi   = (R > 0.f) ? atan2f(gamma, beta) : 0.f;
        g_gate[g][0] = alpha;
        g_gate[g][1] = R;
        g_gate[g][2] = phi;
        g_gate[g][3] = t[3];        // sW
        g_gate[g][4] = gp.b[g][0];  // bias
    }
}

// ======================= Kernel B: x projection ============================
// z[t,b,g] = x[t,b,:] . Wg[0,:512] + (b0_g - phi_g).   One warp per row.
__global__ __launch_bounds__(256) void proj_kernel(
    const float* __restrict__ x,
    const float* __restrict__ Wf, const float* __restrict__ Wi,
    const float* __restrict__ Wg, const float* __restrict__ Wo)
{
    __shared__ float4 wsh[D_INPUT];   // wsh[e] = {wf,wi,wg,wo} for element e
    __shared__ float  tb[4];

    const int tid = threadIdx.x;
    for (int e = tid; e < D_INPUT; e += 256)
        wsh[e] = make_float4(Wf[e], Wi[e], Wg[e], Wo[e]);
    if (tid < 4)
        tb[tid] = g_gate[tid][4] - g_gate[tid][2];   // b0 - phi
    __syncthreads();

    const int warp = tid >> 5, lane = tid & 31;
    const int row  = blockIdx.x * 8 + warp;          // 4096 blocks x 8 warps = 32768 rows
    const float4* xr = reinterpret_cast<const float4*>(x + (size_t)row * D_INPUT);

    float a0 = 0.f, a1 = 0.f, a2 = 0.f, a3 = 0.f;
    #pragma unroll
    for (int it = 0; it < 4; ++it) {
        int e4 = it * 32 + lane;          // float4 index; elements 4*e4 .. 4*e4+3
        float4 xv = xr[e4];
        float4 w0 = wsh[e4 * 4 + 0];
        float4 w1 = wsh[e4 * 4 + 1];
        float4 w2 = wsh[e4 * 4 + 2];
        float4 w3 = wsh[e4 * 4 + 3];
        a0 += xv.x * w0.x + xv.y * w1.x + xv.z * w2.x + xv.w * w3.x;
        a1 += xv.x * w0.y + xv.y * w1.y + xv.z * w2.y + xv.w * w3.y;
        a2 += xv.x * w0.z + xv.y * w1.z + xv.z * w2.z + xv.w * w3.z;
        a3 += xv.x * w0.w + xv.y * w1.w + xv.z * w2.w + xv.w * w3.w;
    }
    #pragma unroll
    for (int off = 16; off; off >>= 1) {
        a0 += __shfl_xor_sync(0xffffffffu, a0, off);
        a1 += __shfl_xor_sync(0xffffffffu, a1, off);
        a2 += __shfl_xor_sync(0xffffffffu, a2, off);
        a3 += __shfl_xor_sync(0xffffffffu, a3, off);
    }
    if (lane == 0)
        g_z[row] = make_float4(a0 + tb[0], a1 + tb[1], a2 + tb[2], a3 + tb[3]);
}

// ======================= Kernel C: scalar scan =============================
__device__ __forceinline__ float tanh_ex(float x) {
    // accurate enough (exp approx err ~2^-22): tanh(x) = 1 - 2/(e^{2x}+1)
    float e = __expf(2.f * x);
    return 1.f - __fdividef(2.f, e + 1.f);
}

__global__ void scan_kernel() {
    const int b = threadIdx.x;   // 0..127

    // gate order: 0=f, 1=i, 2=g, 3=o
    const float af = g_gate[0][0], Rf = g_gate[0][1], swf = g_gate[0][3];
    const float ai = g_gate[1][0], Ri = g_gate[1][1], swi = g_gate[1][3];
    const float ag = g_gate[2][0], Rg = g_gate[2][1], swg = g_gate[2][3];
    const float ao = g_gate[3][0], Ro = g_gate[3][1], swo = g_gate[3][3];

    // sigmoid(E) = 0.5 + 0.5*tanh(E/2): fold the halving into the constants
    const float haf = 0.5f * af, hRf = 0.5f * Rf;
    const float hai = 0.5f * ai, hRi = 0.5f * Ri;
    const float hao = 0.5f * ao, hRo = 0.5f * Ro;

    float h = 0.f, c = 0.f;
    float4 z = g_z[b];
    for (int t = 0; t < T_STEPS; ++t) {
        float4 zn = (t + 1 < T_STEPS) ? g_z[(t + 1) * BATCH + b] : z;  // prefetch

        float f  = 0.5f + 0.5f * tanh_ex(fmaf(hRf, __cosf(fmaf(h, swf, z.x)), haf));
        float ig = 0.5f + 0.5f * tanh_ex(fmaf(hRi, __cosf(fmaf(h, swi, z.y)), hai));
        float gg =               tanh_ex(fmaf(Rg,  __cosf(fmaf(h, swg, z.z)), ag));
        float og = 0.5f + 0.5f * tanh_ex(fmaf(hRo, __cosf(fmaf(h, swo, z.w)), hao));

        c = fmaf(f, c, ig * gg);
        h = og * tanh_ex(c);

        g_h[t * BATCH + b] = h;
        z = zn;
    }
    g_cfin[b] = c;
}

// ======================= Kernel D: broadcast write =========================
// out layout: outputs (T,B,512) ++ hx (B,512) ++ cx (B,512); every row of 512
// floats is a single scalar broadcast. One float4 store per thread.
__global__ __launch_bounds__(256) void bcast_kernel(float4* __restrict__ out, int n4) {
    int gid = blockIdx.x * blockDim.x + threadIdx.x;
    if (gid >= n4) return;
    int row = gid >> 7;   // 128 float4 per 512-float row
    float v;
    if (row < ROWS) {
        v = g_h[row];
    } else if (row < ROWS + BATCH) {
        v = g_h[(T_STEPS - 1) * BATCH + (row - ROWS)];        // hx == last h
    } else {
        v = g_cfin[row - ROWS - BATCH];                        // cx
    }
    out[gid] = make_float4(v, v, v, v);
}

// ======================= launch ============================================
extern "C" void kernel_launch(void* const* d_in, const int* in_sizes, int n_in,
                              void* d_out, int out_size) {
    const float* x = (const float*)d_in[0];

    GatePtrs gp;
    gp.W[0] = (const float*)d_in[1];  gp.b[0] = (const float*)d_in[2];  gp.P[0] = (const float*)d_in[3];
    gp.W[1] = (const float*)d_in[4];  gp.b[1] = (const float*)d_in[5];  gp.P[1] = (const float*)d_in[6];
    gp.W[2] = (const float*)d_in[7];  gp.b[2] = (const float*)d_in[8];  gp.P[2] = (const float*)d_in[9];
    gp.W[3] = (const float*)d_in[10]; gp.b[3] = (const float*)d_in[11]; gp.P[3] = (const float*)d_in[12];

    gate_const_kernel<<<4, 256>>>(gp);
    proj_kernel<<<ROWS / 8, 256>>>(x, gp.W[0], gp.W[1], gp.W[2], gp.W[3]);
    scan_kernel<<<1, BATCH>>>();

    int n4 = out_size / 4;
    bcast_kernel<<<(n4 + 255) / 256, 256>>>((float4*)d_out, n4);
}